// round 7
// baseline (speedup 1.0000x reference)
#include <cuda_runtime.h>
#include <math.h>

// ---------------------------------------------------------------------------
// QRNN: h_t = tanh(x_t @ Wh + b + h_{t-1} @ Uh),  T=512, B=32, D=1024
// Mega-kernel: the recurrence CTAs self-produce their wh = x@Wh + b tiles
// in registers, 4-step lookahead, filling the FFMA idle between steps.
// No separate SGEMM kernel; no extra synchronization (own-tile production).
// h-GEMM topology and flag protocol identical to the proven R6 kernel.
// ---------------------------------------------------------------------------

#define TT 512
#define BB 32
#define DD 1024
#define QQ 256

#define HS_STRIDE 1036
#define PART_STRIDE 264

// smem float offsets
#define OFF_US   0
#define OFF_HS   (32 * 1024)                       // 32768
#define OFF_PART (OFF_HS + 8 * HS_STRIDE)          // 41056
#define OFF_XS   (OFF_PART + 8 * PART_STRIDE)      // 43168
#define OFF_WHS  (OFF_XS + 4096)                   // 47264
#define SMEM_FLOATS (OFF_WHS + 4096)               // 51360 -> 205440 B

__device__ float g_Wh[DD * DD];
__device__ float g_Uh[DD * DD];
__device__ int   g_done[TT][4][32];   // per (t, batch-group, ntile) flag

// ------------------------- sync primitives ----------------------------------
__device__ __forceinline__ int ld_acq(const int* p) {
    int v;
    asm volatile("ld.acquire.gpu.global.s32 %0, [%1];" : "=r"(v) : "l"(p) : "memory");
    return v;
}
__device__ __forceinline__ void st_rel(int* p, int v) {
    asm volatile("st.release.gpu.global.s32 [%0], %1;" :: "l"(p), "r"(v) : "memory");
}

// --------------------------- flag reset -------------------------------------
__global__ void zero_flags_kernel() {
    int i = blockIdx.x * blockDim.x + threadIdx.x;
    if (i < TT * 4 * 32) (&g_done[0][0][0])[i] = 0;
}

// --------------------------- quaternion matrix build ------------------------
__global__ void build_qmat_kernel(const float* __restrict__ wr,
                                  const float* __restrict__ wi,
                                  const float* __restrict__ wj,
                                  const float* __restrict__ wk,
                                  int which) {
    int e = blockIdx.x * blockDim.x + threadIdx.x;
    int d = blockIdx.y;
    int br = d >> 8, bc = e >> 8;
    int r = d & 255, c = e & 255;
    int comp = br ^ bc;
    int mask = (0x5390 >> (br * 4)) & 0xF;
    float s = ((mask >> bc) & 1) ? -1.0f : 1.0f;
    const float* w = (comp == 0) ? wr : (comp == 1) ? wi : (comp == 2) ? wj : wk;
    float* W = which ? g_Uh : g_Wh;
    W[d * DD + e] = s * w[r * QQ + c];
}

// --------------------------- wh production pass -----------------------------
// One pass = K-chunk [p*128, p*128+128) of window w (timesteps 4w..4w+3).
// Each thread (r = tid>>5, c = tid&31) accumulates 4 outputs (one per t').
__device__ __forceinline__ void wh_pass(const float* __restrict__ x,
                                        float* xs, float* whs,
                                        int n, int g, int tid,
                                        int w, int p, float acc[4]) {
    int kb = p << 7;
    // stage x chunk: xs[i][r][kk], 4 t' x 8 rows x 128 k
#pragma unroll
    for (int m = 0; m < 4; ++m) {
        int I = (tid + (m << 8)) << 2;
        int i = I >> 10, r2 = (I >> 7) & 7, kk = I & 127;
        *(float4*)&xs[I] = *(const float4*)
            &x[(size_t)(4 * w + i) * (BB * DD) + (size_t)(g * 8 + r2) * DD + kb + kk];
    }
    // stage Wh chunk: whs[k][c], 128 k x 32 cols (linear copy of slab rows)
#pragma unroll
    for (int m = 0; m < 4; ++m) {
        int I = (tid + (m << 8)) << 2;
        int k = I >> 5, c2 = I & 31;
        *(float4*)&whs[I] = *(const float4*)&g_Wh[(size_t)(kb + k) * DD + n * 32 + c2];
    }
    __syncthreads();

    const float* xr = &xs[((tid >> 5) & 7) << 7];   // row base (i stride 1024)
    int c2 = tid & 31;
#pragma unroll 8
    for (int kk = 0; kk < 128; kk += 4) {
        float4 x0 = *(const float4*)&xr[kk];
        float4 x1 = *(const float4*)&xr[1024 + kk];
        float4 x2 = *(const float4*)&xr[2048 + kk];
        float4 x3 = *(const float4*)&xr[3072 + kk];
        float w0 = whs[(kk + 0) * 32 + c2];
        float w1 = whs[(kk + 1) * 32 + c2];
        float w2 = whs[(kk + 2) * 32 + c2];
        float w3 = whs[(kk + 3) * 32 + c2];
        acc[0] += x0.x * w0; acc[0] += x0.y * w1; acc[0] += x0.z * w2; acc[0] += x0.w * w3;
        acc[1] += x1.x * w0; acc[1] += x1.y * w1; acc[1] += x1.z * w2; acc[1] += x1.w * w3;
        acc[2] += x2.x * w0; acc[2] += x2.y * w1; acc[2] += x2.z * w2; acc[2] += x2.w * w3;
        acc[3] += x3.x * w0; acc[3] += x3.y * w1; acc[3] += x3.z * w2; acc[3] += x3.w * w3;
    }
    __syncthreads();   // protect xs/whs before next pass restages
}

// --------------------------- fused recurrence --------------------------------
__global__ void __launch_bounds__(256)
recur_kernel(float* __restrict__ out, const float* __restrict__ x,
             const float* __restrict__ bias) {
    extern __shared__ float sm[];
    float* Us   = sm + OFF_US;      // [1024][32]
    float* hs   = sm + OFF_HS;      // [8][HS_STRIDE]
    float* part = sm + OFF_PART;    // [8][PART_STRIDE]
    float* xs   = sm + OFF_XS;      // [4][8][128]
    float* whs  = sm + OFF_WHS;     // [128][32]

    int tid = threadIdx.x;
    int n = blockIdx.x >> 2;        // ntile 0..31
    int g = blockIdx.x & 3;         // batch group 0..3

    int ob = tid >> 5, oc = tid & 31;
    size_t obase = (size_t)(g * 8 + ob) * DD + n * 32 + oc;
    float bias_c = bias[n * 32 + oc];

    // load Uh column slab: Us[k][c] = Uh[k][n*32+c]
    for (int i = tid; i < 1024 * 8; i += 256) {
        int k = i >> 3, c4 = (i & 7) << 2;
        *(float4*)&Us[k * 32 + c4] =
            *(const float4*)&g_Uh[(size_t)k * DD + n * 32 + c4];
    }
    __syncthreads();

    // ---- prologue: produce wh windows 0 (-> wh_reg) and 1 (-> pend) ----
    float wh_reg[4], pend[4], acc[4];
#pragma unroll
    for (int i = 0; i < 4; ++i) acc[i] = bias_c;
    for (int p = 0; p < 8; ++p) wh_pass(x, xs, whs, n, g, tid, 0, p, acc);
#pragma unroll
    for (int i = 0; i < 4; ++i) { wh_reg[i] = acc[i]; acc[i] = bias_c; }
    for (int p = 0; p < 8; ++p) wh_pass(x, xs, whs, n, g, tid, 1, p, acc);
#pragma unroll
    for (int i = 0; i < 4; ++i) pend[i] = acc[i];

    // ---- t = 0: h0 = tanh(wh[0]) ----
    out[obase] = tanhf(wh_reg[0]);
    __syncthreads();
    if (tid == 0) { __threadfence(); st_rel(&g_done[0][g][n], 1); }

    int lane = tid & 31, w = tid >> 5;
    int bg = (lane >> 3) << 1;                 // 0,2,4,6 : 2 batch rows
    int cg = (lane & 7) << 2;                  // 0..28   : 4 cols
    const int kbase = w << 7;                  // warp's K slice

    for (int t = 1; t < TT; ++t) {
        if ((t & 3) == 0) {
#pragma unroll
            for (int i = 0; i < 4; ++i) wh_reg[i] = pend[i];
        }
        float whv = wh_reg[t & 3];

        // parallel poll: warp 0's 32 lanes each watch one producer flag
        if (w == 0) {
            const int* fp = &g_done[t - 1][g][lane];
            int rdy = (ld_acq(fp) != 0);
            while (!__all_sync(0xffffffffu, rdy)) {
                if (!rdy) rdy = (ld_acq(fp) != 0);
            }
        }
        __syncthreads();

        // stage h_{t-1} rows of this batch group: 8 x 1024
        const float* hrow = out + (size_t)(t - 1) * BB * DD + (size_t)(g * 8) * DD;
        for (int i = tid; i < 2048; i += 256) {
            int b = i >> 8, k4 = (i & 255) << 2;
            *(float4*)&hs[b * HS_STRIDE + k4] =
                *(const float4*)&hrow[(size_t)b * DD + k4];
        }
        __syncthreads();

        float a0[4] = {0.f, 0.f, 0.f, 0.f};
        float a1[4] = {0.f, 0.f, 0.f, 0.f};
        const float* h0p = &hs[bg * HS_STRIDE + kbase];
        const float* h1p = &hs[(bg + 1) * HS_STRIDE + kbase];
        const float* up  = &Us[kbase * 32 + cg];

#pragma unroll 4
        for (int kk = 0; kk < 128; kk += 4) {
            float h0v[4], h1v[4];
            *(float4*)h0v = *(const float4*)&h0p[kk];
            *(float4*)h1v = *(const float4*)&h1p[kk];
#pragma unroll
            for (int q = 0; q < 4; q++) {
                float uv[4];
                *(float4*)uv = *(const float4*)&up[(kk + q) * 32];
#pragma unroll
                for (int j = 0; j < 4; j++) {
                    a0[j] += h0v[q] * uv[j];
                    a1[j] += h1v[q] * uv[j];
                }
            }
        }

        // intra-CTA split-K reduce through SMEM (fixed order => deterministic)
        *(float4*)&part[w * PART_STRIDE + bg * 32 + cg]       = *(float4*)a0;
        *(float4*)&part[w * PART_STRIDE + (bg + 1) * 32 + cg] = *(float4*)a1;
        __syncthreads();

        float s = whv;
#pragma unroll
        for (int ww = 0; ww < 8; ww++) s += part[ww * PART_STRIDE + tid];
        out[(size_t)t * BB * DD + obase] = tanhf(s);

        __syncthreads();
        if (tid == 0) { __threadfence(); st_rel(&g_done[t][g][n], 1); }

        // ---- wh production: 2 passes per step, windows >= 2 ----
#pragma unroll
        for (int j = 0; j < 2; ++j) {
            int P = 2 * (t - 1) + j;
            int wnd = 2 + (P >> 3);
            if (wnd < 128) {
                int p = P & 7;
                if (p == 0) {
#pragma unroll
                    for (int i = 0; i < 4; ++i) acc[i] = bias_c;
                }
                wh_pass(x, xs, whs, n, g, tid, wnd, p, acc);
                if (p == 7) {
#pragma unroll
                    for (int i = 0; i < 4; ++i) pend[i] = acc[i];
                }
            }
        }
    }
}

// --------------------------- launch ------------------------------------------
extern "C" void kernel_launch(void* const* d_in, const int* in_sizes, int n_in,
                              void* d_out, int out_size) {
    const float* x    = (const float*)d_in[0];
    const float* wh_r = (const float*)d_in[1];
    const float* wh_i = (const float*)d_in[2];
    const float* wh_j = (const float*)d_in[3];
    const float* wh_k = (const float*)d_in[4];
    const float* uh_r = (const float*)d_in[5];
    const float* uh_i = (const float*)d_in[6];
    const float* uh_j = (const float*)d_in[7];
    const float* uh_k = (const float*)d_in[8];
    const float* wh_b = (const float*)d_in[9];
    float* out = (float*)d_out;

    zero_flags_kernel<<<(TT * 4 * 32 + 255) / 256, 256>>>();

    dim3 bq(DD / 256, DD);
    build_qmat_kernel<<<bq, 256>>>(wh_r, wh_i, wh_j, wh_k, 0);
    build_qmat_kernel<<<bq, 256>>>(uh_r, uh_i, uh_j, uh_k, 1);

    const int smem_bytes = SMEM_FLOATS * 4;   // ~205 KB
    cudaFuncSetAttribute(recur_kernel,
                         cudaFuncAttributeMaxDynamicSharedMemorySize, smem_bytes);
    recur_kernel<<<32 * 4, 256, smem_bytes>>>(out, x, wh_b);
}

// round 8
// speedup vs baseline: 1.2133x; 1.2133x over previous
#include <cuda_runtime.h>
#include <math.h>

// ---------------------------------------------------------------------------
// QRNN: h_t = tanh(x_t @ Wh + b + h_{t-1} @ Uh),  T=512, B=32, D=1024
// Phase B: fp32 SGEMM (R3-proven).
// Phase C: R6 recurrence topology (128 CTAs = 32 ntiles x 4 batch groups,
//          full-K per CTA, warp-split-K, SMEM reduce) with:
//            - per-warp streamed chunk staging (poll producer 4w+c, LDG->STS,
//              overlap next chunk's LDG with current chunk's compute)
//            - release stores without redundant __threadfence
// ---------------------------------------------------------------------------

#define TT 512
#define BB 32
#define DD 1024
#define QQ 256

#define HS_STRIDE 1036
#define PART_STRIDE 264

__device__ float g_Wh[DD * DD];
__device__ float g_Uh[DD * DD];
__device__ int   g_done[TT][4][32];   // per (t, batch-group, ntile) flag

// ------------------------- sync primitives ----------------------------------
__device__ __forceinline__ int ld_acq(const int* p) {
    int v;
    asm volatile("ld.acquire.gpu.global.s32 %0, [%1];" : "=r"(v) : "l"(p) : "memory");
    return v;
}
__device__ __forceinline__ void st_rel(int* p, int v) {
    asm volatile("st.release.gpu.global.s32 [%0], %1;" :: "l"(p), "r"(v) : "memory");
}

// --------------------------- flag reset -------------------------------------
__global__ void zero_flags_kernel() {
    int i = blockIdx.x * blockDim.x + threadIdx.x;
    if (i < TT * 4 * 32) (&g_done[0][0][0])[i] = 0;
}

// --------------------------- quaternion matrix build ------------------------
__global__ void build_qmat_kernel(const float* __restrict__ wr,
                                  const float* __restrict__ wi,
                                  const float* __restrict__ wj,
                                  const float* __restrict__ wk,
                                  int which) {
    int e = blockIdx.x * blockDim.x + threadIdx.x;
    int d = blockIdx.y;
    int br = d >> 8, bc = e >> 8;
    int r = d & 255, c = e & 255;
    int comp = br ^ bc;
    int mask = (0x5390 >> (br * 4)) & 0xF;
    float s = ((mask >> bc) & 1) ? -1.0f : 1.0f;
    const float* w = (comp == 0) ? wr : (comp == 1) ? wi : (comp == 2) ? wj : wk;
    float* W = which ? g_Uh : g_Wh;
    W[d * DD + e] = s * w[r * QQ + c];
}

// --------------------------- fp32 SGEMM (R3 version) ------------------------
#define GBM 128
#define GBN 128
#define GBK 8

__global__ void __launch_bounds__(256)
sgemm_bias_kernel(const float* __restrict__ A, const float* __restrict__ bias,
                  float* __restrict__ C, int M, int N, int K) {
    __shared__ float As[2][GBK][GBM];
    __shared__ float Bs[2][GBK][GBN];
    const float* Bmat = g_Wh;

    int tid  = threadIdx.x;
    int brow = blockIdx.y, bcol = blockIdx.x;
    int arow = tid >> 1,  acol = (tid & 1) << 2;
    int brl  = tid >> 5,  bcl  = (tid & 31) << 2;

    const float* Ab = A + (size_t)(brow * GBM) * K;
    const float* Bb = Bmat + bcol * GBN;

    float4 av = *(const float4*)&Ab[(size_t)arow * K + acol];
    float4 bv = *(const float4*)&Bb[(size_t)brl * N + bcl];
    As[0][acol + 0][arow] = av.x;
    As[0][acol + 1][arow] = av.y;
    As[0][acol + 2][arow] = av.z;
    As[0][acol + 3][arow] = av.w;
    *(float4*)&Bs[0][brl][bcl] = bv;
    __syncthreads();

    int tm = (tid >> 4) << 3;
    int tn = (tid & 15) << 3;
    float acc[8][8];
#pragma unroll
    for (int i = 0; i < 8; i++)
#pragma unroll
        for (int j = 0; j < 8; j++) acc[i][j] = 0.0f;

    int nk = K / GBK;
    for (int kt = 0; kt < nk; ++kt) {
        int cur = kt & 1;
        float4 an, bn;
        if (kt + 1 < nk) {
            an = *(const float4*)&Ab[(size_t)arow * K + (kt + 1) * GBK + acol];
            bn = *(const float4*)&Bb[(size_t)((kt + 1) * GBK + brl) * N + bcl];
        }
#pragma unroll
        for (int kk = 0; kk < GBK; kk++) {
            float ra[8], rb[8];
            *(float4*)&ra[0] = *(const float4*)&As[cur][kk][tm];
            *(float4*)&ra[4] = *(const float4*)&As[cur][kk][tm + 4];
            *(float4*)&rb[0] = *(const float4*)&Bs[cur][kk][tn];
            *(float4*)&rb[4] = *(const float4*)&Bs[cur][kk][tn + 4];
#pragma unroll
            for (int i = 0; i < 8; i++)
#pragma unroll
                for (int j = 0; j < 8; j++) acc[i][j] += ra[i] * rb[j];
        }
        if (kt + 1 < nk) {
            int nxt = cur ^ 1;
            As[nxt][acol + 0][arow] = an.x;
            As[nxt][acol + 1][arow] = an.y;
            As[nxt][acol + 2][arow] = an.z;
            As[nxt][acol + 3][arow] = an.w;
            *(float4*)&Bs[nxt][brl][bcl] = bn;
            __syncthreads();
        }
    }

    float bias_r[8];
#pragma unroll
    for (int j = 0; j < 8; j++) bias_r[j] = bias[bcol * GBN + tn + j];
#pragma unroll
    for (int i = 0; i < 8; i++) {
        float4 v0 = make_float4(acc[i][0] + bias_r[0], acc[i][1] + bias_r[1],
                                acc[i][2] + bias_r[2], acc[i][3] + bias_r[3]);
        float4 v1 = make_float4(acc[i][4] + bias_r[4], acc[i][5] + bias_r[5],
                                acc[i][6] + bias_r[6], acc[i][7] + bias_r[7]);
        size_t row = (size_t)(brow * GBM + tm + i) * N + bcol * GBN + tn;
        *(float4*)&C[row]     = v0;
        *(float4*)&C[row + 4] = v1;
    }
}

// --------------------------- recurrence -------------------------------------
// CTA (n, g): output tile = batch rows [g*8, g*8+8) x cols [n*32, n*32+32),
// full K=1024. Uh[:, n*32..n*32+32) resident in SMEM (128 KB).
// Warp w owns K slice [w*128, w*128+128) = producer ntiles 4w..4w+3.
// Per step, per warp: stream 4 chunks of 32 k: wait flag -> LDG (regs) ->
// STS -> syncwarp -> compute, with next chunk's LDG overlapping compute.
// Then SMEM split-K reduce (unchanged), tanh, STG, release own flag.
__global__ void __launch_bounds__(256)
recur_kernel(float* __restrict__ out) {
    extern __shared__ float sm[];
    float* Us   = sm;                          // [1024][32]
    float* hs   = Us + 1024 * 32;              // [8][HS_STRIDE]
    float* part = hs + 8 * HS_STRIDE;          // [8][PART_STRIDE]

    int tid = threadIdx.x;
    int n = blockIdx.x >> 2;                   // 0..31 ntile
    int g = blockIdx.x & 3;                    // 0..3 batch group

    // load Uh column slab: Us[k][c] = Uh[k][n*32+c]
    for (int i = tid; i < 1024 * 8; i += 256) {
        int k = i >> 3, c4 = (i & 7) << 2;
        *(float4*)&Us[k * 32 + c4] =
            *(const float4*)&g_Uh[(size_t)k * DD + n * 32 + c4];
    }

    int ob = tid >> 5, oc = tid & 31;          // this thread's output element
    size_t obase = (size_t)(g * 8 + ob) * DD + n * 32 + oc;

    // t = 0: h0 = tanh(wh_out[0])
    float v0 = out[obase];
    __syncthreads();                           // Us loaded
    out[obase] = tanhf(v0);
    __syncthreads();
    if (tid == 0) st_rel(&g_done[0][g][n], 1);

    int lane = tid & 31, w = tid >> 5;
    int bg = (lane >> 3) << 1;                 // 0,2,4,6 : 2 batch rows
    int cg = (lane & 7) << 2;                  // 0..28   : 4 cols
    const int kbase = w << 7;                  // warp's K slice

    // staging coords for this lane: row sr (0..7), col offset scq (0,8,16,24)
    int sr  = lane >> 2;
    int scq = (lane & 3) << 3;

    for (int t = 1; t < TT; ++t) {
        // prefetch wh for this step (exclusively ours)
        float whv = __ldcg(&out[(size_t)t * BB * DD + obase]);

        const float* hrow = out + (size_t)(t - 1) * BB * DD
                          + (size_t)(g * 8 + sr) * DD + kbase + scq;
        const int* fbase = &g_done[t - 1][g][w << 2];

        float a0[4] = {0.f, 0.f, 0.f, 0.f};
        float a1[4] = {0.f, 0.f, 0.f, 0.f};

        // chunk 0: wait + load
        while (ld_acq(&fbase[0]) == 0) { }
        float4 p0 = *(const float4*)&hrow[0];
        float4 p1 = *(const float4*)&hrow[4];

#pragma unroll
        for (int c = 0; c < 4; ++c) {
            // stage chunk c into hs
            float* dst = &hs[sr * HS_STRIDE + kbase + (c << 5) + scq];
            *(float4*)&dst[0] = p0;
            *(float4*)&dst[4] = p1;
            __syncwarp();

            // wait + issue loads for chunk c+1 (overlaps compute below)
            if (c < 3) {
                while (ld_acq(&fbase[c + 1]) == 0) { }
                p0 = *(const float4*)&hrow[(c + 1) << 5];
                p1 = *(const float4*)&hrow[((c + 1) << 5) + 4];
            }

            // compute chunk c: k in [kbase+32c, kbase+32c+32)
            const float* h0p = &hs[bg * HS_STRIDE + kbase + (c << 5)];
            const float* h1p = &hs[(bg + 1) * HS_STRIDE + kbase + (c << 5)];
            const float* up  = &Us[(kbase + (c << 5)) * 32 + cg];
#pragma unroll
            for (int kk = 0; kk < 32; kk += 4) {
                float h0v[4], h1v[4];
                *(float4*)h0v = *(const float4*)&h0p[kk];
                *(float4*)h1v = *(const float4*)&h1p[kk];
#pragma unroll
                for (int q = 0; q < 4; q++) {
                    float uv[4];
                    *(float4*)uv = *(const float4*)&up[(kk + q) * 32];
#pragma unroll
                    for (int j = 0; j < 4; j++) {
                        a0[j] += h0v[q] * uv[j];
                        a1[j] += h1v[q] * uv[j];
                    }
                }
            }
            __syncwarp();   // all lanes done reading chunk before restaging
        }

        // intra-CTA split-K reduce through SMEM (fixed order => deterministic)
        *(float4*)&part[w * PART_STRIDE + bg * 32 + cg]       = *(float4*)a0;
        *(float4*)&part[w * PART_STRIDE + (bg + 1) * 32 + cg] = *(float4*)a1;
        __syncthreads();

        float s = whv;
#pragma unroll
        for (int ww = 0; ww < 8; ww++) s += part[ww * PART_STRIDE + tid];
        out[(size_t)t * BB * DD + obase] = tanhf(s);

        __syncthreads();                       // all STGs issued before release
        if (t < TT - 1 && tid == 0) st_rel(&g_done[t][g][n], 1);
    }
}

// --------------------------- launch ------------------------------------------
extern "C" void kernel_launch(void* const* d_in, const int* in_sizes, int n_in,
                              void* d_out, int out_size) {
    const float* x    = (const float*)d_in[0];
    const float* wh_r = (const float*)d_in[1];
    const float* wh_i = (const float*)d_in[2];
    const float* wh_j = (const float*)d_in[3];
    const float* wh_k = (const float*)d_in[4];
    const float* uh_r = (const float*)d_in[5];
    const float* uh_i = (const float*)d_in[6];
    const float* uh_j = (const float*)d_in[7];
    const float* uh_k = (const float*)d_in[8];
    const float* wh_b = (const float*)d_in[9];
    float* out = (float*)d_out;

    zero_flags_kernel<<<(TT * 4 * 32 + 255) / 256, 256>>>();

    dim3 bq(DD / 256, DD);
    build_qmat_kernel<<<bq, 256>>>(wh_r, wh_i, wh_j, wh_k, 0);
    build_qmat_kernel<<<bq, 256>>>(uh_r, uh_i, uh_j, uh_k, 1);

    dim3 gg(DD / GBN, (TT * BB) / GBM);   // (8, 128)
    sgemm_bias_kernel<<<gg, 256>>>(x, wh_b, out, TT * BB, DD, DD);

    const int smem_bytes = (1024 * 32 + 8 * HS_STRIDE + 8 * PART_STRIDE) * 4;
    cudaFuncSetAttribute(recur_kernel,
                         cudaFuncAttributeMaxDynamicSharedMemorySize, smem_bytes);
    recur_kernel<<<32 * 4, 256, smem_bytes>>>(out);
}

// round 10
// speedup vs baseline: 1.6905x; 1.3933x over previous
#include <cuda_runtime.h>
#include <math.h>

// ---------------------------------------------------------------------------
// QRNN: h_t = tanh(x_t @ Wh + b + h_{t-1} @ Uh),  T=512, B=32, D=1024
// Phase B: fp32 SGEMM (R3-proven).
// Phase C: R6 recurrence (128 CTAs = 32 ntiles x 4 batch groups, full-K per
//          CTA, warp-split-K, SMEM reduce, per-CTA release flags).
//          Release via st.release right after __syncthreads (no extra fence),
//          no release at the last timestep.
// zero_flags folded into the Wh build launch (4 launches per iteration).
// ---------------------------------------------------------------------------

#define TT 512
#define BB 32
#define DD 1024
#define QQ 256

#define HS_STRIDE 1036
#define PART_STRIDE 264

__device__ float g_Wh[DD * DD];
__device__ float g_Uh[DD * DD];
__device__ int   g_done[TT][4][32];   // per (t, batch-group, ntile) flag

// ------------------------- sync primitives ----------------------------------
__device__ __forceinline__ int ld_acq(const int* p) {
    int v;
    asm volatile("ld.acquire.gpu.global.s32 %0, [%1];" : "=r"(v) : "l"(p) : "memory");
    return v;
}
__device__ __forceinline__ void st_rel(int* p, int v) {
    asm volatile("st.release.gpu.global.s32 [%0], %1;" :: "l"(p), "r"(v) : "memory");
}

// --------------------------- quaternion matrix build ------------------------
// which==0 also zeroes the flag array (rides along off the critical path).
__global__ void build_qmat_kernel(const float* __restrict__ wr,
                                  const float* __restrict__ wi,
                                  const float* __restrict__ wj,
                                  const float* __restrict__ wk,
                                  int which) {
    int e = blockIdx.x * blockDim.x + threadIdx.x;
    int d = blockIdx.y;
    if (which == 0 && d == 0) {
        for (int i = e; i < TT * 4 * 32; i += 1024)
            (&g_done[0][0][0])[i] = 0;
    }
    int br = d >> 8, bc = e >> 8;
    int r = d & 255, c = e & 255;
    int comp = br ^ bc;
    int mask = (0x5390 >> (br * 4)) & 0xF;
    float s = ((mask >> bc) & 1) ? -1.0f : 1.0f;
    const float* w = (comp == 0) ? wr : (comp == 1) ? wi : (comp == 2) ? wj : wk;
    float* W = which ? g_Uh : g_Wh;
    W[d * DD + e] = s * w[r * QQ + c];
}

// --------------------------- fp32 SGEMM (R3 version) ------------------------
#define GBM 128
#define GBN 128
#define GBK 8

__global__ void __launch_bounds__(256)
sgemm_bias_kernel(const float* __restrict__ A, const float* __restrict__ bias,
                  float* __restrict__ C, int M, int N, int K) {
    __shared__ float As[2][GBK][GBM];
    __shared__ float Bs[2][GBK][GBN];
    const float* Bmat = g_Wh;

    int tid  = threadIdx.x;
    int brow = blockIdx.y, bcol = blockIdx.x;
    int arow = tid >> 1,  acol = (tid & 1) << 2;
    int brl  = tid >> 5,  bcl  = (tid & 31) << 2;

    const float* Ab = A + (size_t)(brow * GBM) * K;
    const float* Bb = Bmat + bcol * GBN;

    float4 av = *(const float4*)&Ab[(size_t)arow * K + acol];
    float4 bv = *(const float4*)&Bb[(size_t)brl * N + bcl];
    As[0][acol + 0][arow] = av.x;
    As[0][acol + 1][arow] = av.y;
    As[0][acol + 2][arow] = av.z;
    As[0][acol + 3][arow] = av.w;
    *(float4*)&Bs[0][brl][bcl] = bv;
    __syncthreads();

    int tm = (tid >> 4) << 3;
    int tn = (tid & 15) << 3;
    float acc[8][8];
#pragma unroll
    for (int i = 0; i < 8; i++)
#pragma unroll
        for (int j = 0; j < 8; j++) acc[i][j] = 0.0f;

    int nk = K / GBK;
    for (int kt = 0; kt < nk; ++kt) {
        int cur = kt & 1;
        float4 an, bn;
        if (kt + 1 < nk) {
            an = *(const float4*)&Ab[(size_t)arow * K + (kt + 1) * GBK + acol];
            bn = *(const float4*)&Bb[(size_t)((kt + 1) * GBK + brl) * N + bcl];
        }
#pragma unroll
        for (int kk = 0; kk < GBK; kk++) {
            float ra[8], rb[8];
            *(float4*)&ra[0] = *(const float4*)&As[cur][kk][tm];
            *(float4*)&ra[4] = *(const float4*)&As[cur][kk][tm + 4];
            *(float4*)&rb[0] = *(const float4*)&Bs[cur][kk][tn];
            *(float4*)&rb[4] = *(const float4*)&Bs[cur][kk][tn + 4];
#pragma unroll
            for (int i = 0; i < 8; i++)
#pragma unroll
                for (int j = 0; j < 8; j++) acc[i][j] += ra[i] * rb[j];
        }
        if (kt + 1 < nk) {
            int nxt = cur ^ 1;
            As[nxt][acol + 0][arow] = an.x;
            As[nxt][acol + 1][arow] = an.y;
            As[nxt][acol + 2][arow] = an.z;
            As[nxt][acol + 3][arow] = an.w;
            *(float4*)&Bs[nxt][brl][bcl] = bn;
            __syncthreads();
        }
    }

    float bias_r[8];
#pragma unroll
    for (int j = 0; j < 8; j++) bias_r[j] = bias[bcol * GBN + tn + j];
#pragma unroll
    for (int i = 0; i < 8; i++) {
        float4 v0 = make_float4(acc[i][0] + bias_r[0], acc[i][1] + bias_r[1],
                                acc[i][2] + bias_r[2], acc[i][3] + bias_r[3]);
        float4 v1 = make_float4(acc[i][4] + bias_r[4], acc[i][5] + bias_r[5],
                                acc[i][6] + bias_r[6], acc[i][7] + bias_r[7]);
        size_t row = (size_t)(brow * GBM + tm + i) * N + bcol * GBN + tn;
        *(float4*)&C[row]     = v0;
        *(float4*)&C[row + 4] = v1;
    }
}

// --------------------------- recurrence (R6 body) ----------------------------
__global__ void __launch_bounds__(256)
recur_kernel(float* __restrict__ out) {
    extern __shared__ float sm[];
    float* Us   = sm;                          // [1024][32]
    float* hs   = Us + 1024 * 32;              // [8][HS_STRIDE]
    float* part = hs + 8 * HS_STRIDE;          // [8][PART_STRIDE]

    int tid = threadIdx.x;
    int n = blockIdx.x >> 2;                   // 0..31 ntile
    int g = blockIdx.x & 3;                    // 0..3 batch group

    // load Uh column slab: Us[k][c] = Uh[k][n*32+c]
    for (int i = tid; i < 1024 * 8; i += 256) {
        int k = i >> 3, c4 = (i & 7) << 2;
        *(float4*)&Us[k * 32 + c4] =
            *(const float4*)&g_Uh[(size_t)k * DD + n * 32 + c4];
    }

    int ob = tid >> 5, oc = tid & 31;          // this thread's output element
    size_t obase = (size_t)(g * 8 + ob) * DD + n * 32 + oc;

    // t = 0: h0 = tanh(wh_out[0])
    float v0 = out[obase];
    __syncthreads();                           // Us loaded
    out[obase] = tanhf(v0);
    __syncthreads();
    if (tid == 0) st_rel(&g_done[0][g][n], 1);

    int lane = tid & 31, w = tid >> 5;
    int bg = (lane >> 3) << 1;                 // 0,2,4,6 : 2 batch rows
    int cg = (lane & 7) << 2;                  // 0..28   : 4 cols
    const int kbase = w << 7;                  // warp's K slice

    for (int t = 1; t < TT; ++t) {
        // prefetch wh for this step (exclusively ours) before the wait
        float whv = __ldcg(&out[(size_t)t * BB * DD + obase]);

        // parallel poll: warp 0's 32 lanes each watch one producer flag
        if (w == 0) {
            const int* fp = &g_done[t - 1][g][lane];
            int rdy = (ld_acq(fp) != 0);
            while (!__all_sync(0xffffffffu, rdy)) {
                if (!rdy) rdy = (ld_acq(fp) != 0);
            }
        }
        __syncthreads();

        // stage h_{t-1} rows of this batch group: 8 x 1024
        const float* hrow = out + (size_t)(t - 1) * BB * DD + (size_t)(g * 8) * DD;
        for (int i = tid; i < 2048; i += 256) {        // float4 granularity
            int b = i >> 8, k4 = (i & 255) << 2;
            *(float4*)&hs[b * HS_STRIDE + k4] =
                *(const float4*)&hrow[(size_t)b * DD + k4];
        }
        __syncthreads();

        float a0[4] = {0.f, 0.f, 0.f, 0.f};
        float a1[4] = {0.f, 0.f, 0.f, 0.f};
        const float* h0p = &hs[bg * HS_STRIDE + kbase];
        const float* h1p = &hs[(bg + 1) * HS_STRIDE + kbase];
        const float* up  = &Us[kbase * 32 + cg];

#pragma unroll 4
        for (int kk = 0; kk < 128; kk += 4) {
            float h0v[4], h1v[4];
            *(float4*)h0v = *(const float4*)&h0p[kk];
            *(float4*)h1v = *(const float4*)&h1p[kk];
#pragma unroll
            for (int q = 0; q < 4; q++) {
                float uv[4];
                *(float4*)uv = *(const float4*)&up[(kk + q) * 32];
#pragma unroll
                for (int j = 0; j < 4; j++) {
                    a0[j] += h0v[q] * uv[j];
                    a1[j] += h1v[q] * uv[j];
                }
            }
        }

        // intra-CTA split-K reduce through SMEM (fixed order => deterministic)
        *(float4*)&part[w * PART_STRIDE + bg * 32 + cg]       = *(float4*)a0;
        *(float4*)&part[w * PART_STRIDE + (bg + 1) * 32 + cg] = *(float4*)a1;
        __syncthreads();

        float s = whv;
#pragma unroll
        for (int ww = 0; ww < 8; ww++) s += part[ww * PART_STRIDE + tid];
        out[(size_t)t * BB * DD + obase] = tanhf(s);

        __syncthreads();                       // all STGs issued before release
        if (t < TT - 1 && tid == 0) st_rel(&g_done[t][g][n], 1);
    }
}

// --------------------------- launch ------------------------------------------
extern "C" void kernel_launch(void* const* d_in, const int* in_sizes, int n_in,
                              void* d_out, int out_size) {
    const float* x    = (const float*)d_in[0];
    const float* wh_r = (const float*)d_in[1];
    const float* wh_i = (const float*)d_in[2];
    const float* wh_j = (const float*)d_in[3];
    const float* wh_k = (const float*)d_in[4];
    const float* uh_r = (const float*)d_in[5];
    const float* uh_i = (const float*)d_in[6];
    const float* uh_j = (const float*)d_in[7];
    const float* uh_k = (const float*)d_in[8];
    const float* wh_b = (const float*)d_in[9];
    float* out = (float*)d_out;

    dim3 bq(DD / 256, DD);
    build_qmat_kernel<<<bq, 256>>>(wh_r, wh_i, wh_j, wh_k, 0);  // also zeroes flags
    build_qmat_kernel<<<bq, 256>>>(uh_r, uh_i, uh_j, uh_k, 1);

    dim3 gg(DD / GBN, (TT * BB) / GBM);   // (8, 128)
    sgemm_bias_kernel<<<gg, 256>>>(x, wh_b, out, TT * BB, DD, DD);

    const int smem_bytes = (1024 * 32 + 8 * HS_STRIDE + 8 * PART_STRIDE) * 4;
    cudaFuncSetAttribute(recur_kernel,
                         cudaFuncAttributeMaxDynamicSharedMemorySize, smem_bytes);
    recur_kernel<<<32 * 4, 256, smem_bytes>>>(out);
}